// round 2
// baseline (speedup 1.0000x reference)
#include <cuda_runtime.h>
#include <math.h>

// DAGMixer: per-row gated mix, persistent-CTA pipelined version.
//   logits[row] = dot(orig[row], W[0:H]) + dot(dag[row], W[H:2H]) + b
//   gate = sigmoid(logits)
//   mixed[row] = orig[row] + gate * (dag[row] - orig[row])
//
// 608 persistent CTAs (152 SMs x 4), 256 threads. Each thread holds:
//   - its 16 W floats in registers for the whole kernel
//   - current row (16 floats) + prefetched next row (16 floats) in registers
// Next-row LDGs are issued BEFORE the reduce barrier so DRAM never idles
// during the reduce/sigmoid window. One __syncthreads per row; warpsum
// buffer is parity double-buffered to avoid a second barrier.

#define THREADS 256
#define H_DIM   2048
#define V4      2            // (H_DIM/4)/THREADS
#define NWARP   (THREADS/32)
#define GRID_CTAS 608        // 152 SMs * 4 CTAs

__global__ __launch_bounds__(THREADS, 4)
void dagmixer_kernel(const float* __restrict__ orig,
                     const float* __restrict__ dag,
                     const float* __restrict__ w,      // [2H]: W_o then W_d
                     const float* __restrict__ bgate,  // [1]
                     float* __restrict__ mixed,        // [rows*H]
                     float* __restrict__ gate_out,     // [rows]
                     int rows)
{
    const int tid    = threadIdx.x;
    const int lane   = tid & 31;
    const int wid    = tid >> 5;
    const int stride = gridDim.x;

    int row = blockIdx.x;
    if (row >= rows) return;

    // W slice for this thread lives in registers for the whole kernel.
    float4 wo[V4], wd[V4];
    #pragma unroll
    for (int k = 0; k < V4; k++) {
        const int idx = tid + k * THREADS;
        wo[k] = ((const float4*)w)[idx];
        wd[k] = ((const float4*)(w + H_DIM))[idx];
    }
    const float bias = bgate[0];

    __shared__ float warpsum[2][NWARP];
    int parity = 0;

    float4 ov[V4], dv[V4], ov2[V4], dv2[V4];

    // Preload first row.
    {
        const float4* o4 = (const float4*)(orig + (size_t)row * H_DIM);
        const float4* d4 = (const float4*)(dag  + (size_t)row * H_DIM);
        #pragma unroll
        for (int k = 0; k < V4; k++) {
            const int idx = tid + k * THREADS;
            ov[k] = o4[idx];
            dv[k] = d4[idx];
        }
    }

    for (; row < rows; row += stride) {
        // Prefetch next row BEFORE the reduce barrier: keeps LDGs in flight
        // while this CTA reduces/syncs.
        const int nrow = row + stride;
        if (nrow < rows) {
            const float4* o4 = (const float4*)(orig + (size_t)nrow * H_DIM);
            const float4* d4 = (const float4*)(dag  + (size_t)nrow * H_DIM);
            #pragma unroll
            for (int k = 0; k < V4; k++) {
                const int idx = tid + k * THREADS;
                ov2[k] = o4[idx];
                dv2[k] = d4[idx];
            }
        }

        // Partial dot against register-resident W.
        float partial = 0.0f;
        #pragma unroll
        for (int k = 0; k < V4; k++) {
            partial = fmaf(ov[k].x, wo[k].x, partial);
            partial = fmaf(ov[k].y, wo[k].y, partial);
            partial = fmaf(ov[k].z, wo[k].z, partial);
            partial = fmaf(ov[k].w, wo[k].w, partial);
            partial = fmaf(dv[k].x, wd[k].x, partial);
            partial = fmaf(dv[k].y, wd[k].y, partial);
            partial = fmaf(dv[k].z, wd[k].z, partial);
            partial = fmaf(dv[k].w, wd[k].w, partial);
        }

        // Warp reduce.
        #pragma unroll
        for (int off = 16; off > 0; off >>= 1)
            partial += __shfl_xor_sync(0xffffffff, partial, off);

        if (lane == 0) warpsum[parity][wid] = partial;
        __syncthreads();   // single barrier per row

        // All threads redundantly finish the reduce + sigmoid (no broadcast barrier).
        float s = bias;
        #pragma unroll
        for (int i = 0; i < NWARP; i++) s += warpsum[parity][i];
        const float g = 1.0f / (1.0f + __expf(-s));
        if (tid == 0) gate_out[row] = g;

        // Mix from registers and store.
        float4* m4 = (float4*)(mixed + (size_t)row * H_DIM);
        #pragma unroll
        for (int k = 0; k < V4; k++) {
            const int idx = tid + k * THREADS;
            float4 r;
            r.x = fmaf(g, dv[k].x - ov[k].x, ov[k].x);
            r.y = fmaf(g, dv[k].y - ov[k].y, ov[k].y);
            r.z = fmaf(g, dv[k].z - ov[k].z, ov[k].z);
            r.w = fmaf(g, dv[k].w - ov[k].w, ov[k].w);
            m4[idx] = r;
        }

        // Rotate double buffers.
        #pragma unroll
        for (int k = 0; k < V4; k++) { ov[k] = ov2[k]; dv[k] = dv2[k]; }
        parity ^= 1;
    }
}

extern "C" void kernel_launch(void* const* d_in, const int* in_sizes, int n_in,
                              void* d_out, int out_size)
{
    const float* orig  = (const float*)d_in[0];  // original_hidden [B,T,H]
    const float* dag   = (const float*)d_in[1];  // dag_hidden      [B,T,H]
    const float* wgate = (const float*)d_in[2];  // W_gate          [2H,1]
    const float* bgate = (const float*)d_in[3];  // b_gate          [1]

    const int total = in_sizes[0];               // B*T*H
    const int rows  = total / H_DIM;             // B*T

    float* mixed    = (float*)d_out;             // first B*T*H floats
    float* gate_out = (float*)d_out + total;     // then B*T gate values

    const int grid = (rows < GRID_CTAS) ? rows : GRID_CTAS;
    dagmixer_kernel<<<grid, THREADS>>>(orig, dag, wgate, bgate, mixed, gate_out, rows);
}

// round 3
// speedup vs baseline: 1.0070x; 1.0070x over previous
#include <cuda_runtime.h>
#include <math.h>

// DAGMixer: per-row gated mix, persistent-CTA pipelined version (R3).
//   logits[row] = dot(orig[row], W[0:H]) + dot(dag[row], W[H:2H]) + b
//   gate = sigmoid(logits); mixed[row] = orig + gate*(dag - orig)
//
// 608 persistent CTAs (152 SMs x 4), 256 threads. Per thread: 16 W floats in
// registers for the whole kernel; current row (16f) + prefetched next row
// (16f) in registers. Prefetch is issued before the reduce barrier.
// R3 changes vs R2: pointer-increment addressing (no per-iter IMAD.WIDE),
// branchless prefetch clamp (no tail dead-window), __ldcs/__stcs streaming
// hints, unroll-2 to elide buffer-rotation copies.

#define THREADS 256
#define H_DIM   2048
#define F4_ROW  (H_DIM / 4)   // 512 float4 per row
#define V4      2             // F4_ROW / THREADS
#define NWARP   (THREADS / 32)
#define GRID_CTAS 608         // 152 SMs * 4 CTAs

__global__ __launch_bounds__(THREADS, 4)
void dagmixer_kernel(const float* __restrict__ orig,
                     const float* __restrict__ dag,
                     const float* __restrict__ w,      // [2H]: W_o then W_d
                     const float* __restrict__ bgate,  // [1]
                     float* __restrict__ mixed,        // [rows*H]
                     float* __restrict__ gate_out,     // [rows]
                     int rows)
{
    const int tid  = threadIdx.x;
    const int lane = tid & 31;
    const int wid  = tid >> 5;

    int row = blockIdx.x;
    if (row >= rows) return;

    const size_t stride_f4 = (size_t)gridDim.x * F4_ROW;  // row stride in float4
    const int    stride    = gridDim.x;

    // Base pointers for this thread, advanced by stride_f4 each iteration.
    const float4* po = (const float4*)orig + (size_t)row * F4_ROW + tid;
    const float4* pd = (const float4*)dag  + (size_t)row * F4_ROW + tid;
    float4*       pm = (float4*)mixed      + (size_t)row * F4_ROW + tid;

    // W slice in registers for the whole kernel.
    float4 wo[V4], wd[V4];
    #pragma unroll
    for (int k = 0; k < V4; k++) {
        wo[k] = ((const float4*)w)[tid + k * THREADS];
        wd[k] = ((const float4*)(w + H_DIM))[tid + k * THREADS];
    }
    const float bias = bgate[0];

    __shared__ float warpsum[2][NWARP];
    int parity = 0;

    float4 ov[V4], dv[V4];

    // Preload first row (streaming hint: use-once data).
    #pragma unroll
    for (int k = 0; k < V4; k++) {
        ov[k] = __ldcs(po + k * THREADS);
        dv[k] = __ldcs(pd + k * THREADS);
    }

    #pragma unroll 2
    for (; row < rows; row += stride) {
        // Branchless prefetch clamp: last iteration re-reads the current row
        // (in-bounds, L2-hit) instead of predicating loads off.
        const bool has_next = (row + stride) < rows;
        const float4* pno = has_next ? (po + stride_f4) : po;
        const float4* pnd = has_next ? (pd + stride_f4) : pd;

        float4 ov2[V4], dv2[V4];
        #pragma unroll
        for (int k = 0; k < V4; k++) {
            ov2[k] = __ldcs(pno + k * THREADS);
            dv2[k] = __ldcs(pnd + k * THREADS);
        }

        // Partial dot against register-resident W.
        float partial = 0.0f;
        #pragma unroll
        for (int k = 0; k < V4; k++) {
            partial = fmaf(ov[k].x, wo[k].x, partial);
            partial = fmaf(ov[k].y, wo[k].y, partial);
            partial = fmaf(ov[k].z, wo[k].z, partial);
            partial = fmaf(ov[k].w, wo[k].w, partial);
            partial = fmaf(dv[k].x, wd[k].x, partial);
            partial = fmaf(dv[k].y, wd[k].y, partial);
            partial = fmaf(dv[k].z, wd[k].z, partial);
            partial = fmaf(dv[k].w, wd[k].w, partial);
        }

        // Warp reduce.
        #pragma unroll
        for (int off = 16; off > 0; off >>= 1)
            partial += __shfl_xor_sync(0xffffffff, partial, off);

        if (lane == 0) warpsum[parity][wid] = partial;
        __syncthreads();   // single barrier per row

        // All threads redundantly finish the reduce + sigmoid.
        float s = bias;
        #pragma unroll
        for (int i = 0; i < NWARP; i++) s += warpsum[parity][i];
        const float g = 1.0f / (1.0f + __expf(-s));
        if (tid == 0) gate_out[row] = g;

        // Mix from registers, streaming store.
        #pragma unroll
        for (int k = 0; k < V4; k++) {
            float4 r;
            r.x = fmaf(g, dv[k].x - ov[k].x, ov[k].x);
            r.y = fmaf(g, dv[k].y - ov[k].y, ov[k].y);
            r.z = fmaf(g, dv[k].z - ov[k].z, ov[k].z);
            r.w = fmaf(g, dv[k].w - ov[k].w, ov[k].w);
            __stcs(pm + k * THREADS, r);
        }

        // Advance pointers; rotate buffers (elided by renaming under unroll).
        po = pno;
        pd = pnd;
        pm += stride_f4;
        #pragma unroll
        for (int k = 0; k < V4; k++) { ov[k] = ov2[k]; dv[k] = dv2[k]; }
        parity ^= 1;
    }
}

extern "C" void kernel_launch(void* const* d_in, const int* in_sizes, int n_in,
                              void* d_out, int out_size)
{
    const float* orig  = (const float*)d_in[0];  // original_hidden [B,T,H]
    const float* dag   = (const float*)d_in[1];  // dag_hidden      [B,T,H]
    const float* wgate = (const float*)d_in[2];  // W_gate          [2H,1]
    const float* bgate = (const float*)d_in[3];  // b_gate          [1]

    const int total = in_sizes[0];               // B*T*H
    const int rows  = total / H_DIM;             // B*T

    float* mixed    = (float*)d_out;             // first B*T*H floats
    float* gate_out = (float*)d_out + total;     // then B*T gate values

    const int grid = (rows < GRID_CTAS) ? rows : GRID_CTAS;
    dagmixer_kernel<<<grid, THREADS>>>(orig, dag, wgate, bgate, mixed, gate_out, rows);
}